// round 1
// baseline (speedup 1.0000x reference)
#include <cuda_runtime.h>
#include <cuda_bf16.h>
#include <math.h>

// ---------------- problem constants ----------------
#define Bsz   65536
#define Cdim  2
#define Vdim  3
#define Ddim  64
#define Kcb   1024
#define Sst   4
#define Hdim  1024
#define Ldim  5
#define Fdim  25
#define INdim 102
#define INpad 104

// ---------------- scratch (device globals: allocation-free) ----------------
__device__ float g_pe[(size_t)Bsz * INpad];
__device__ float g_h0[(size_t)Bsz * Hdim];
__device__ float g_h1[(size_t)Bsz * Hdim];
__device__ float g_zq[Ddim];
__device__ float g_bias[Ldim * Hdim];
__device__ float g_loss;
__device__ int   g_idx[Sst];

// ---------------- helpers ----------------
__device__ __forceinline__ unsigned long long fma2(unsigned long long c,
                                                   unsigned long long a,
                                                   unsigned long long b) {
    unsigned long long d;
    asm("fma.rn.f32x2 %0, %1, %2, %3;" : "=l"(d) : "l"(a), "l"(b), "l"(c));
    return d;
}
__device__ __forceinline__ unsigned long long dup2(float x) {
    unsigned long long r;
    unsigned xi = __float_as_uint(x);
    asm("mov.b64 %0, {%1, %1};" : "=l"(r) : "r"(xi));
    return r;
}
__device__ __forceinline__ float lo32(unsigned long long v) {
    return __uint_as_float((unsigned)(v & 0xffffffffULL));
}
__device__ __forceinline__ float hi32(unsigned long long v) {
    return __uint_as_float((unsigned)(v >> 32));
}

// Accurate sin/cos for large args (robust even under --use_fast_math):
// double Cody-Waite reduction by pi, then small-angle sinf/cosf.
__device__ __forceinline__ void sincos_acc(float a, float* s, float* c) {
    double ad = (double)a;
    double kd = rint(ad * 0.31830988618379067154);       // a / pi
    double r  = fma(-kd, 3.141592653589793116e+00, ad);  // pi hi
    r         = fma(-kd, 1.2246467991473531772e-16, r);  // pi lo
    float rf = (float)r;                                 // |rf| <= pi/2
    float sr = sinf(rf), cr = cosf(rf);
    if (((long long)kd) & 1LL) { sr = -sr; cr = -cr; }
    *s = sr; *c = cr;
}

// ---------------- stage 1: RVQ (forward values only) ----------------
// Forward of z_q_st is z itself => z_q_sum = sum_s img[s]; idx_s = argmin dist.
__global__ void vq_kernel(const float* __restrict__ latents,
                          const int*   __restrict__ lidx,
                          const float* __restrict__ cb) {
    __shared__ float z[Ddim];
    __shared__ float rv[256];
    __shared__ int   ri[256];
    __shared__ float zz_sh;
    __shared__ float loss_sh;
    int t = threadIdx.x;
    const float* img = latents + (size_t)lidx[0] * Sst * Ddim;
    if (t == 0) loss_sh = 0.f;

    for (int s = 0; s < Sst; s++) {
        if (t < Ddim) z[t] = img[s * Ddim + t];
        __syncthreads();
        if (t == 0) {
            float acc = 0.f;
            for (int d = 0; d < Ddim; d++) acc += z[d] * z[d];
            zz_sh = acc;
        }
        __syncthreads();
        float best = 3.4e38f; int bi = 0x7fffffff;
        for (int k = t; k < Kcb; k += 256) {
            const float* e = cb + ((size_t)s * Kcb + k) * Ddim;
            float dot = 0.f, ee = 0.f;
            #pragma unroll 8
            for (int d = 0; d < Ddim; d++) { float ev = e[d]; dot += z[d] * ev; ee += ev * ev; }
            float dist = zz_sh - 2.f * dot + ee;
            if (dist < best) { best = dist; bi = k; }
        }
        rv[t] = best; ri[t] = bi;
        __syncthreads();
        for (int off = 128; off > 0; off >>= 1) {
            if (t < off) {
                if (rv[t + off] < rv[t] || (rv[t + off] == rv[t] && ri[t + off] < ri[t])) {
                    rv[t] = rv[t + off]; ri[t] = ri[t + off];
                }
            }
            __syncthreads();
        }
        if (t == 0) {
            int idx = ri[0];
            g_idx[s] = idx;
            const float* e = cb + ((size_t)s * Kcb + idx) * Ddim;
            float acc = 0.f;
            for (int d = 0; d < Ddim; d++) { float df = e[d] - z[d]; acc += df * df; }
            loss_sh += 0.25f * (acc / (float)Ddim);
        }
        __syncthreads();
    }
    if (t < Ddim)
        g_zq[t] = img[t] + img[Ddim + t] + img[2 * Ddim + t] + img[3 * Ddim + t];
    if (t == 0) g_loss = loss_sh;
}

// ---------------- stage 2: fused per-layer bias = dec_b + beta ----------------
__global__ void beta_kernel(const float* __restrict__ modW, const float* __restrict__ modb,
                            const float* __restrict__ db0,  const float* __restrict__ dbh) {
    int i = blockIdx.x * blockDim.x + threadIdx.x;
    if (i >= Ldim * Hdim) return;
    int l = i >> 10, h = i & 1023;
    float acc = modb[i] + ((l == 0) ? db0[h] : dbh[(size_t)(l - 1) * Hdim + h]);
    #pragma unroll 8
    for (int d = 0; d < Ddim; d++)
        acc += g_zq[d] * modW[((size_t)l * Ddim + d) * Hdim + h];
    g_bias[i] = acc;
}

// ---------------- stage 3: positional encoding ----------------
__global__ void pe_kernel(const float* __restrict__ coords) {
    int b = blockIdx.x * blockDim.x + threadIdx.x;
    if (b >= Bsz) return;
    float x = coords[2 * b], y = coords[2 * b + 1];
    float* row = g_pe + (size_t)b * INpad;
    row[0] = x; row[1] = y;
    row[102] = 0.f; row[103] = 0.f;     // zero pad columns
    const float PI_F = 3.14159274101257324219f;  // float(pi), matches jnp
    float freq = 1.f;
    for (int f = 0; f < Fdim; f++) {
        float fp = freq * PI_F;          // fp32, same as XLA
        float ax = x * fp, ay = y * fp;  // fp32, same as XLA
        float sx, cx, sy, cy;
        sincos_acc(ax, &sx, &cx);
        sincos_acc(ay, &sy, &cy);
        row[2 + 4 * f + 0] = sx;
        row[2 + 4 * f + 1] = sy;
        row[2 + 4 * f + 2] = cx;
        row[2 + 4 * f + 3] = cy;
        freq *= 2.f;
    }
}

// ---------------- stage 4: SGEMM with fma.rn.f32x2 ----------------
// C[M x 1024] = act(A[M x K] @ W[K x 1024] + bias), 128x128x8 tiles,
// 256 threads, 8x8 micro-tile as 4x8 f32x2 pairs. B duplicated in SMEM so the
// inner loop is LDS.64 (conflict-free via n = tx + 16*j) + FFMA2 only.
__global__ __launch_bounds__(256, 2)
void sgemm_kernel(const float* __restrict__ A, int lda, int K,
                  const float* __restrict__ W,
                  const float* __restrict__ bias,
                  float* __restrict__ C, int relu) {
    __shared__ float As[8][128];
    __shared__ float Bd[8][256];   // duplicated pairs: Bd[k][2n]=Bd[k][2n+1]=W[k][n0+n]
    const int tid = threadIdx.x;
    const int tx = tid & 15, ty = tid >> 4;
    const int m0 = blockIdx.y * 128;
    const int n0 = blockIdx.x * 128;
    const int aRow = tid >> 1, aCol = (tid & 1) * 4;
    const int wRow = tid >> 5, wLane = tid & 31;

    unsigned long long acc[4][8];
    #pragma unroll
    for (int i = 0; i < 4; i++)
        #pragma unroll
        for (int j = 0; j < 8; j++) acc[i][j] = 0ULL;

    const int ktiles = lda / 8;   // lda is the zero-padded K
    for (int kt = 0; kt < ktiles; kt++) {
        const int k0 = kt * 8;
        // A tile -> SMEM (transposed)
        float4 av = *(const float4*)(A + (size_t)(m0 + aRow) * lda + k0 + aCol);
        As[aCol + 0][aRow] = av.x;
        As[aCol + 1][aRow] = av.y;
        As[aCol + 2][aRow] = av.z;
        As[aCol + 3][aRow] = av.w;
        // W tile -> SMEM duplicated (conflict-free STS.64, coalesced LDG)
        {
            unsigned long long* Bp = (unsigned long long*)&Bd[wRow][0];
            const int krow = k0 + wRow;
            #pragma unroll
            for (int q = 0; q < 4; q++) {
                int n = wLane + 32 * q;
                float v = (krow < K) ? W[(size_t)krow * Hdim + n0 + n] : 0.f;
                Bp[n] = dup2(v);
            }
        }
        __syncthreads();
        #pragma unroll
        for (int kk = 0; kk < 8; kk++) {
            const unsigned long long* Ap = (const unsigned long long*)&As[kk][0];
            const unsigned long long* Bq = (const unsigned long long*)&Bd[kk][0];
            unsigned long long a2[4], b2[8];
            #pragma unroll
            for (int i = 0; i < 4; i++) a2[i] = Ap[ty * 4 + i];       // broadcast
            #pragma unroll
            for (int j = 0; j < 8; j++) b2[j] = Bq[tx + 16 * j];      // stride-8B
            #pragma unroll
            for (int i = 0; i < 4; i++)
                #pragma unroll
                for (int j = 0; j < 8; j++)
                    acc[i][j] = fma2(acc[i][j], a2[i], b2[j]);
        }
        __syncthreads();
    }
    // epilogue
    float bv[8];
    #pragma unroll
    for (int j = 0; j < 8; j++) bv[j] = bias[n0 + tx + 16 * j];
    #pragma unroll
    for (int i = 0; i < 4; i++) {
        const int m = m0 + ty * 8 + 2 * i;
        float* Cl = C + (size_t)m * Hdim;
        float* Ch = Cl + Hdim;
        #pragma unroll
        for (int j = 0; j < 8; j++) {
            int n = n0 + tx + 16 * j;
            float vl = lo32(acc[i][j]) + bv[j];
            float vh = hi32(acc[i][j]) + bv[j];
            if (relu) { vl = fmaxf(vl, 0.f); vh = fmaxf(vh, 0.f); }
            Cl[n] = vl;
            Ch[n] = vh;
        }
    }
}

// ---------------- stage 5: final 1024 -> 3 projection ----------------
__global__ void out_kernel(const float* __restrict__ Hin, const float* __restrict__ Wout,
                           const float* __restrict__ bout, float* __restrict__ out) {
    __shared__ float sW[Hdim * Vdim];
    __shared__ float sb[Vdim];
    int tid = threadIdx.x;
    for (int i = tid; i < Hdim * Vdim; i += 256) sW[i] = Wout[i];
    if (tid < Vdim) sb[tid] = bout[tid];
    __syncthreads();
    int warp = tid >> 5, lane = tid & 31;
    int r = blockIdx.x * 8 + warp;
    const float* hr = Hin + (size_t)r * Hdim;
    float a0 = 0.f, a1 = 0.f, a2 = 0.f;
    for (int k = lane * 4; k < Hdim; k += 128) {
        float4 hv = *(const float4*)(hr + k);
        a0 += hv.x * sW[k*3]   + hv.y * sW[(k+1)*3]   + hv.z * sW[(k+2)*3]   + hv.w * sW[(k+3)*3];
        a1 += hv.x * sW[k*3+1] + hv.y * sW[(k+1)*3+1] + hv.z * sW[(k+2)*3+1] + hv.w * sW[(k+3)*3+1];
        a2 += hv.x * sW[k*3+2] + hv.y * sW[(k+1)*3+2] + hv.z * sW[(k+2)*3+2] + hv.w * sW[(k+3)*3+2];
    }
    #pragma unroll
    for (int off = 16; off > 0; off >>= 1) {
        a0 += __shfl_xor_sync(0xffffffffu, a0, off);
        a1 += __shfl_xor_sync(0xffffffffu, a1, off);
        a2 += __shfl_xor_sync(0xffffffffu, a2, off);
    }
    if (lane == 0) {
        out[(size_t)r * 3 + 0] = a0 + sb[0];
        out[(size_t)r * 3 + 1] = a1 + sb[1];
        out[(size_t)r * 3 + 2] = a2 + sb[2];
    }
}

// ---------------- stage 6: tail outputs (idxs, loss) ----------------
__global__ void tail_kernel(float* __restrict__ out, int out_size) {
    int t = threadIdx.x;
    const int base = Bsz * Vdim;
    int extra = out_size - base;
    if (t < extra) {
        float v = 0.f;
        if (t < Sst)       v = (float)g_idx[t];
        else if (t == Sst) v = g_loss;
        out[base + t] = v;
    }
}

// ---------------- launch ----------------
extern "C" void kernel_launch(void* const* d_in, const int* in_sizes, int n_in,
                              void* d_out, int out_size) {
    const float* coords    = (const float*)d_in[0];
    const int*   lidx      = (const int*)  d_in[1];
    const float* latents   = (const float*)d_in[2];
    const float* codebooks = (const float*)d_in[3];
    const float* modW      = (const float*)d_in[4];
    const float* modb      = (const float*)d_in[5];
    const float* W0        = (const float*)d_in[6];
    const float* b0        = (const float*)d_in[7];
    const float* Wh        = (const float*)d_in[8];
    const float* bh        = (const float*)d_in[9];
    const float* Wout      = (const float*)d_in[10];
    const float* bout      = (const float*)d_in[11];
    float* out = (float*)d_out;

    float *pe, *h0, *h1, *bias;
    cudaGetSymbolAddress((void**)&pe,   g_pe);
    cudaGetSymbolAddress((void**)&h0,   g_h0);
    cudaGetSymbolAddress((void**)&h1,   g_h1);
    cudaGetSymbolAddress((void**)&bias, g_bias);

    vq_kernel<<<1, 256>>>(latents, lidx, codebooks);
    beta_kernel<<<(Ldim * Hdim + 255) / 256, 256>>>(modW, modb, b0, bh);
    pe_kernel<<<Bsz / 256, 256>>>(coords);

    dim3 grid(Hdim / 128, Bsz / 128);
    sgemm_kernel<<<grid, 256>>>(pe, INpad, INdim, W0,                        bias,            h0, 1);
    sgemm_kernel<<<grid, 256>>>(h0, Hdim,  Hdim,  Wh + (size_t)0 * Hdim * Hdim, bias + 1 * Hdim, h1, 1);
    sgemm_kernel<<<grid, 256>>>(h1, Hdim,  Hdim,  Wh + (size_t)1 * Hdim * Hdim, bias + 2 * Hdim, h0, 1);
    sgemm_kernel<<<grid, 256>>>(h0, Hdim,  Hdim,  Wh + (size_t)2 * Hdim * Hdim, bias + 3 * Hdim, h1, 1);
    sgemm_kernel<<<grid, 256>>>(h1, Hdim,  Hdim,  Wh + (size_t)3 * Hdim * Hdim, bias + 4 * Hdim, h0, 1);
    out_kernel<<<Bsz / 8, 256>>>(h0, Wout, bout, out);
    tail_kernel<<<1, 256>>>(out, out_size);
}

// round 4
// speedup vs baseline: 1.9710x; 1.9710x over previous
#include <cuda_runtime.h>
#include <cuda_fp16.h>
#include <cstdint>
#include <math.h>

// ---------------- problem constants ----------------
#define Bsz   65536
#define Vdim  3
#define Ddim  64
#define Kcb   1024
#define Sst   4
#define Hdim  1024
#define Ldim  5
#define Fdim  25
#define INdim 102
#define K0ld  128          // layer-0 K padded

// GEMM tiling
#define TM 128
#define TN 128
#define KC 64              // fp16 per K-chunk = 128B rows (SW128 atom)
#define STAGE_BYTES 65536
#define A_HI 0
#define A_LO 16384
#define B_HI 32768
#define B_LO 49152
#define NSTAGE 3
#define SMEM_TOTAL (NSTAGE * STAGE_BYTES)

// ---------------- scratch (device globals: allocation-free) ----------------
__device__ __align__(256) __half g_peh[(size_t)Bsz * K0ld];
__device__ __align__(256) __half g_pel[(size_t)Bsz * K0ld];
__device__ __align__(256) __half g_xh[(size_t)Bsz * Hdim];
__device__ __align__(256) __half g_xl[(size_t)Bsz * Hdim];
__device__ __align__(256) __half g_yh[(size_t)Bsz * Hdim];
__device__ __align__(256) __half g_yl[(size_t)Bsz * Hdim];
__device__ __align__(256) __half g_w0h[Hdim * K0ld];
__device__ __align__(256) __half g_w0l[Hdim * K0ld];
__device__ __align__(256) __half g_whh[(size_t)4 * Hdim * Hdim];
__device__ __align__(256) __half g_whl[(size_t)4 * Hdim * Hdim];
__device__ float g_bias[Ldim * Hdim];
__device__ float g_zq[Ddim];
__device__ float g_loss;
__device__ int   g_idx[Sst];

// ---------------- PTX helpers (baseline ISA only: sm_80-level) ----------------
__device__ __forceinline__ uint32_t smem_u32(const void* p) {
    uint32_t a;
    asm("{ .reg .u64 t; cvta.to.shared.u64 t, %1; cvt.u32.u64 %0, t; }" : "=r"(a) : "l"(p));
    return a;
}
__device__ __forceinline__ void cpasync16(uint32_t dst, const void* src) {
    asm volatile("cp.async.cg.shared.global [%0], [%1], 16;" :: "r"(dst), "l"(src) : "memory");
}
__device__ __forceinline__ void cp_commit() {
    asm volatile("cp.async.commit_group;" ::: "memory");
}
__device__ __forceinline__ void cp_wait1() {
    asm volatile("cp.async.wait_group 1;" ::: "memory");
}
__device__ __forceinline__ void ldsm4(uint32_t* r, uint32_t addr) {
    asm volatile("ldmatrix.sync.aligned.m8n8.x4.shared.b16 {%0,%1,%2,%3}, [%4];"
        : "=r"(r[0]), "=r"(r[1]), "=r"(r[2]), "=r"(r[3]) : "r"(addr));
}
__device__ __forceinline__ void mma16816(float* d, const uint32_t* a, const uint32_t* b) {
    asm volatile("mma.sync.aligned.m16n8k16.row.col.f32.f16.f16.f32 "
        "{%0,%1,%2,%3}, {%4,%5,%6,%7}, {%8,%9}, {%0,%1,%2,%3};"
        : "+f"(d[0]), "+f"(d[1]), "+f"(d[2]), "+f"(d[3])
        : "r"(a[0]), "r"(a[1]), "r"(a[2]), "r"(a[3]), "r"(b[0]), "r"(b[1]));
}
__device__ __forceinline__ void split1(float v, __half& h, __half& l) {
    h = __float2half_rn(v);
    l = __float2half_rn(v - __half2float(h));
}
__device__ __forceinline__ uint32_t pack2(__half a, __half b) {
    return (uint32_t)__half_as_ushort(a) | ((uint32_t)__half_as_ushort(b) << 16);
}

// Accurate sin/cos for large args (robust under fast-math): double Cody-Waite by pi.
__device__ __forceinline__ void sincos_acc(float a, float* s, float* c) {
    double ad = (double)a;
    double kd = rint(ad * 0.31830988618379067154);
    double r  = fma(-kd, 3.141592653589793116e+00, ad);
    r         = fma(-kd, 1.2246467991473531772e-16, r);
    float rf = (float)r;
    float sr = sinf(rf), cr = cosf(rf);
    if (((long long)kd) & 1LL) { sr = -sr; cr = -cr; }
    *s = sr; *c = cr;
}

// ---------------- stage 1: RVQ (forward values only) ----------------
__global__ void vq_kernel(const float* __restrict__ latents,
                          const int*   __restrict__ lidx,
                          const float* __restrict__ cb) {
    __shared__ float z[Ddim];
    __shared__ float rv[256];
    __shared__ int   ri[256];
    __shared__ float zz_sh;
    __shared__ float loss_sh;
    int t = threadIdx.x;
    const float* img = latents + (size_t)lidx[0] * Sst * Ddim;
    if (t == 0) loss_sh = 0.f;
    for (int s = 0; s < Sst; s++) {
        if (t < Ddim) z[t] = img[s * Ddim + t];
        __syncthreads();
        if (t == 0) {
            float acc = 0.f;
            for (int d = 0; d < Ddim; d++) acc += z[d] * z[d];
            zz_sh = acc;
        }
        __syncthreads();
        float best = 3.4e38f; int bi = 0x7fffffff;
        for (int k = t; k < Kcb; k += 256) {
            const float* e = cb + ((size_t)s * Kcb + k) * Ddim;
            float dot = 0.f, ee = 0.f;
            #pragma unroll 8
            for (int d = 0; d < Ddim; d++) { float ev = e[d]; dot += z[d] * ev; ee += ev * ev; }
            float dist = zz_sh - 2.f * dot + ee;
            if (dist < best) { best = dist; bi = k; }
        }
        rv[t] = best; ri[t] = bi;
        __syncthreads();
        for (int off = 128; off > 0; off >>= 1) {
            if (t < off) {
                if (rv[t + off] < rv[t] || (rv[t + off] == rv[t] && ri[t + off] < ri[t])) {
                    rv[t] = rv[t + off]; ri[t] = ri[t + off];
                }
            }
            __syncthreads();
        }
        if (t == 0) {
            int idx = ri[0];
            g_idx[s] = idx;
            const float* e = cb + ((size_t)s * Kcb + idx) * Ddim;
            float acc = 0.f;
            for (int d = 0; d < Ddim; d++) { float df = e[d] - z[d]; acc += df * df; }
            loss_sh += 0.25f * (acc / (float)Ddim);
        }
        __syncthreads();
    }
    if (t < Ddim)
        g_zq[t] = img[t] + img[Ddim + t] + img[2 * Ddim + t] + img[3 * Ddim + t];
    if (t == 0) g_loss = loss_sh;
}

// ---------------- stage 2: fused per-layer bias = dec_b + beta ----------------
__global__ void beta_kernel(const float* __restrict__ modW, const float* __restrict__ modb,
                            const float* __restrict__ db0,  const float* __restrict__ dbh) {
    int i = blockIdx.x * blockDim.x + threadIdx.x;
    if (i >= Ldim * Hdim) return;
    int l = i >> 10, h = i & 1023;
    float acc = modb[i] + ((l == 0) ? db0[h] : dbh[(size_t)(l - 1) * Hdim + h]);
    #pragma unroll 8
    for (int d = 0; d < Ddim; d++)
        acc += g_zq[d] * modW[((size_t)l * Ddim + d) * Hdim + h];
    g_bias[i] = acc;
}

// ---------------- stage 3: positional encoding -> fp16 hi/lo planes ----------------
__global__ void pe_kernel(const float* __restrict__ coords) {
    int b = blockIdx.x * blockDim.x + threadIdx.x;
    if (b >= Bsz) return;
    float x = coords[2 * b], y = coords[2 * b + 1];
    __half* rh = g_peh + (size_t)b * K0ld;
    __half* rl = g_pel + (size_t)b * K0ld;
    auto st2 = [&](int c, float a, float bv) {
        __half ha, la, hb, lb;
        split1(a, ha, la); split1(bv, hb, lb);
        *(uint32_t*)(rh + c) = pack2(ha, hb);
        *(uint32_t*)(rl + c) = pack2(la, lb);
    };
    st2(0, x, y);
    const float PI_F = 3.14159274101257324219f;
    float freq = 1.f;
    for (int f = 0; f < Fdim; f++) {
        float fp = freq * PI_F;
        float sx, cx, sy, cy;
        sincos_acc(x * fp, &sx, &cx);
        sincos_acc(y * fp, &sy, &cy);
        st2(2 + 4 * f, sx, sy);
        st2(4 + 4 * f, cx, cy);
        freq *= 2.f;
    }
    for (int c = 102; c < K0ld; c += 2) st2(c, 0.f, 0.f);
}

// ---------------- stage 3b: weight transpose + fp16 split ----------------
__global__ void wsplit_kernel(const float* __restrict__ W, int K, int Kld,
                              __half* __restrict__ Whi, __half* __restrict__ Wlo) {
    __shared__ float t[32][33];
    int k0 = blockIdx.x * 32, n0 = blockIdx.y * 32;
    int tx = threadIdx.x, ty = threadIdx.y;   // 32 x 8
    #pragma unroll
    for (int i = 0; i < 32; i += 8) {
        int k = k0 + ty + i;
        t[ty + i][tx] = (k < K) ? W[(size_t)k * Hdim + n0 + tx] : 0.f;
    }
    __syncthreads();
    #pragma unroll
    for (int i = 0; i < 32; i += 8) {
        int n = n0 + ty + i;
        float v = t[tx][ty + i];
        __half h, l; split1(v, h, l);
        Whi[(size_t)n * Kld + k0 + tx] = h;
        Wlo[(size_t)n * Kld + k0 + tx] = l;
    }
}

// ---------------- stage 4: HMMA split-fp16 GEMM ----------------
// O = relu( Ahi@Whi^T + Ahi@Wlo^T + Alo@Whi^T + bias ), outputs split hi/lo fp16.
// 128x128 CTA tile, 8 warps (2x4), warp tile 64x32, K-chunk 64, 3-stage cp.async.
__global__ __launch_bounds__(256, 1)
void gemm_kernel(const __half* __restrict__ Ah, const __half* __restrict__ Al,
                 int Kld, int nch,
                 const __half* __restrict__ Wh, const __half* __restrict__ Wl,
                 const float* __restrict__ bias,
                 __half* __restrict__ Ohi, __half* __restrict__ Olo) {
    extern __shared__ char smem[];
    const uint32_t sbase = smem_u32(smem);
    const int tid  = threadIdx.x;
    const int lane = tid & 31;
    const int w    = tid >> 5;
    const int wm   = w & 1, wn = w >> 1;
    const int m0   = blockIdx.y * TM;
    const int n0   = blockIdx.x * TN;

    const int lrow = tid >> 3;          // 0..31 : load row group
    const int lc16 = tid & 7;           // 0..7  : 16B chunk
    auto load_stage = [&](int c, int buf) {
        const int k0 = c * KC;
        const uint32_t sb = sbase + buf * STAGE_BYTES;
        #pragma unroll
        for (int q = 0; q < 4; q++) {
            int row = lrow + q * 32;
            uint32_t off = ((uint32_t)row << 7) + ((uint32_t)lc16 << 4);
            uint32_t sw  = off ^ ((off >> 3) & 0x70);
            const __half* sa = Ah + (size_t)(m0 + row) * Kld + k0 + lc16 * 8;
            const __half* sl = Al + (size_t)(m0 + row) * Kld + k0 + lc16 * 8;
            const __half* sb_h = Wh + (size_t)(n0 + row) * Kld + k0 + lc16 * 8;
            const __half* sb_l = Wl + (size_t)(n0 + row) * Kld + k0 + lc16 * 8;
            cpasync16(sb + A_HI + sw, sa);
            cpasync16(sb + A_LO + sw, sl);
            cpasync16(sb + B_HI + sw, sb_h);
            cpasync16(sb + B_LO + sw, sb_l);
        }
    };

    load_stage(0, 0); cp_commit();
    load_stage(1, 1); cp_commit();

    float acc[4][4][4];
    #pragma unroll
    for (int mi = 0; mi < 4; mi++)
        #pragma unroll
        for (int ni = 0; ni < 4; ni++)
            #pragma unroll
            for (int e = 0; e < 4; e++) acc[mi][ni][e] = 0.f;

    cp_wait1();
    __syncthreads();

    const int g  = lane >> 3;   // ldmatrix matrix id
    const int rr = lane & 7;

    for (int c = 0; c < nch; c++) {
        const int buf = c % NSTAGE;
        if (c + 2 < nch) load_stage(c + 2, (c + 2) % NSTAGE);
        cp_commit();

        const uint32_t sb = sbase + buf * STAGE_BYTES;
        #pragma unroll
        for (int k16 = 0; k16 < 4; k16++) {
            uint32_t Afh[4][4], Afl[4][4];
            uint32_t Bfh[4][2], Bfl[4][2];
            #pragma unroll
            for (int mi = 0; mi < 4; mi++) {
                int row = wm * 64 + mi * 16 + rr + ((g & 1) << 3);
                int c16 = 2 * k16 + (g >> 1);
                uint32_t off = ((uint32_t)row << 7) + ((uint32_t)c16 << 4);
                uint32_t sw  = off ^ ((off >> 3) & 0x70);
                ldsm4(Afh[mi], sb + A_HI + sw);
                ldsm4(Afl[mi], sb + A_LO + sw);
            }
            #pragma unroll
            for (int nj = 0; nj < 2; nj++) {
                int row = wn * 32 + nj * 16 + rr + ((g >> 1) << 3);
                int c16 = 2 * k16 + (g & 1);
                uint32_t off = ((uint32_t)row << 7) + ((uint32_t)c16 << 4);
                uint32_t sw  = off ^ ((off >> 3) & 0x70);
                uint32_t t[4];
                ldsm4(t, sb + B_HI + sw);
                Bfh[nj * 2][0] = t[0]; Bfh[nj * 2][1] = t[1];
                Bfh[nj * 2 + 1][0] = t[2]; Bfh[nj * 2 + 1][1] = t[3];
                ldsm4(t, sb + B_LO + sw);
                Bfl[nj * 2][0] = t[0]; Bfl[nj * 2][1] = t[1];
                Bfl[nj * 2 + 1][0] = t[2]; Bfl[nj * 2 + 1][1] = t[3];
            }
            #pragma unroll
            for (int mi = 0; mi < 4; mi++)
                #pragma unroll
                for (int ni = 0; ni < 4; ni++) {
                    mma16816(acc[mi][ni], Afh[mi], Bfh[ni]);
                    mma16816(acc[mi][ni], Afh[mi], Bfl[ni]);
                    mma16816(acc[mi][ni], Afl[mi], Bfh[ni]);
                }
        }
        cp_wait1();
        __syncthreads();
    }

    // epilogue: bias + relu + split + store hi/lo planes
    #pragma unroll
    for (int mi = 0; mi < 4; mi++) {
        #pragma unroll
        for (int ni = 0; ni < 4; ni++) {
            int r0 = m0 + wm * 64 + mi * 16 + (lane >> 2);
            int cc = n0 + wn * 32 + ni * 8 + 2 * (lane & 3);
            float b0 = bias[cc], b1 = bias[cc + 1];
            float v0 = fmaxf(acc[mi][ni][0] + b0, 0.f);
            float v1 = fmaxf(acc[mi][ni][1] + b1, 0.f);
            float v2 = fmaxf(acc[mi][ni][2] + b0, 0.f);
            float v3 = fmaxf(acc[mi][ni][3] + b1, 0.f);
            __half h0, l0, h1, l1, h2, l2, h3, l3;
            split1(v0, h0, l0); split1(v1, h1, l1);
            split1(v2, h2, l2); split1(v3, h3, l3);
            *(uint32_t*)(Ohi + (size_t)r0 * Hdim + cc)       = pack2(h0, h1);
            *(uint32_t*)(Olo + (size_t)r0 * Hdim + cc)       = pack2(l0, l1);
            *(uint32_t*)(Ohi + (size_t)(r0 + 8) * Hdim + cc) = pack2(h2, h3);
            *(uint32_t*)(Olo + (size_t)(r0 + 8) * Hdim + cc) = pack2(l2, l3);
        }
    }
}

// ---------------- stage 5: final 1024 -> 3 projection ----------------
__global__ void out_kernel(const __half* __restrict__ Hh, const __half* __restrict__ Hl,
                           const float* __restrict__ Wout, const float* __restrict__ bout,
                           float* __restrict__ out) {
    __shared__ float sW[Hdim * Vdim];
    __shared__ float sb[Vdim];
    int tid = threadIdx.x;
    for (int i = tid; i < Hdim * Vdim; i += 256) sW[i] = Wout[i];
    if (tid < Vdim) sb[tid] = bout[tid];
    __syncthreads();
    int warp = tid >> 5, lane = tid & 31;
    int r = blockIdx.x * 8 + warp;
    const __half* hh = Hh + (size_t)r * Hdim;
    const __half* hl = Hl + (size_t)r * Hdim;
    float a0 = 0.f, a1 = 0.f, a2 = 0.f;
    for (int k = lane * 8; k < Hdim; k += 256) {
        uint4 vh = *(const uint4*)(hh + k);
        uint4 vl = *(const uint4*)(hl + k);
        const uint32_t* uh = (const uint32_t*)&vh;
        const uint32_t* ul = (const uint32_t*)&vl;
        #pragma unroll
        for (int i = 0; i < 4; i++) {
            __half2 bh = *(__half2*)&uh[i];
            __half2 bl = *(__half2*)&ul[i];
            float h0 = __half2float(bh.x) + __half2float(bl.x);
            float h1 = __half2float(bh.y) + __half2float(bl.y);
            int kk = k + 2 * i;
            a0 += h0 * sW[kk * 3]     + h1 * sW[(kk + 1) * 3];
            a1 += h0 * sW[kk * 3 + 1] + h1 * sW[(kk + 1) * 3 + 1];
            a2 += h0 * sW[kk * 3 + 2] + h1 * sW[(kk + 1) * 3 + 2];
        }
    }
    #pragma unroll
    for (int off = 16; off > 0; off >>= 1) {
        a0 += __shfl_xor_sync(0xffffffffu, a0, off);
        a1 += __shfl_xor_sync(0xffffffffu, a1, off);
        a2 += __shfl_xor_sync(0xffffffffu, a2, off);
    }
    if (lane == 0) {
        out[(size_t)r * 3 + 0] = a0 + sb[0];
        out[(size_t)r * 3 + 1] = a1 + sb[1];
        out[(size_t)r * 3 + 2] = a2 + sb[2];
    }
}

// ---------------- stage 6: tail outputs (idxs, loss) ----------------
__global__ void tail_kernel(float* __restrict__ out, int out_size) {
    int t = threadIdx.x;
    const int base = Bsz * Vdim;
    int extra = out_size - base;
    if (t < extra) {
        float v = 0.f;
        if (t < Sst)       v = (float)g_idx[t];
        else if (t == Sst) v = g_loss;
        out[base + t] = v;
    }
}

// ---------------- launch ----------------
extern "C" void kernel_launch(void* const* d_in, const int* in_sizes, int n_in,
                              void* d_out, int out_size) {
    const float* coords    = (const float*)d_in[0];
    const int*   lidx      = (const int*)  d_in[1];
    const float* latents   = (const float*)d_in[2];
    const float* codebooks = (const float*)d_in[3];
    const float* modW      = (const float*)d_in[4];
    const float* modb      = (const float*)d_in[5];
    const float* W0        = (const float*)d_in[6];
    const float* b0        = (const float*)d_in[7];
    const float* Wh        = (const float*)d_in[8];
    const float* bh        = (const float*)d_in[9];
    const float* Wout      = (const float*)d_in[10];
    const float* bout      = (const float*)d_in[11];
    float* out = (float*)d_out;

    __half *peh, *pel, *xh, *xl, *yh, *yl, *w0h, *w0l, *whh, *whl;
    float* bias;
    cudaGetSymbolAddress((void**)&peh, g_peh);
    cudaGetSymbolAddress((void**)&pel, g_pel);
    cudaGetSymbolAddress((void**)&xh,  g_xh);
    cudaGetSymbolAddress((void**)&xl,  g_xl);
    cudaGetSymbolAddress((void**)&yh,  g_yh);
    cudaGetSymbolAddress((void**)&yl,  g_yl);
    cudaGetSymbolAddress((void**)&w0h, g_w0h);
    cudaGetSymbolAddress((void**)&w0l, g_w0l);
    cudaGetSymbolAddress((void**)&whh, g_whh);
    cudaGetSymbolAddress((void**)&whl, g_whl);
    cudaGetSymbolAddress((void**)&bias, g_bias);

    cudaFuncSetAttribute(gemm_kernel, cudaFuncAttributeMaxDynamicSharedMemorySize, SMEM_TOTAL);

    vq_kernel<<<1, 256>>>(latents, lidx, codebooks);
    beta_kernel<<<(Ldim * Hdim + 255) / 256, 256>>>(modW, modb, b0, bh);
    pe_kernel<<<Bsz / 256, 256>>>(coords);

    dim3 tb(32, 8);
    wsplit_kernel<<<dim3(K0ld / 32, Hdim / 32), tb>>>(W0, INdim, K0ld, w0h, w0l);
    for (int l = 0; l < 4; l++)
        wsplit_kernel<<<dim3(Hdim / 32, Hdim / 32), tb>>>(Wh + (size_t)l * Hdim * Hdim, Hdim, Hdim,
                                                          whh + (size_t)l * Hdim * Hdim,
                                                          whl + (size_t)l * Hdim * Hdim);

    dim3 grid(Hdim / TN, Bsz / TM);
    gemm_kernel<<<grid, 256, SMEM_TOTAL>>>(peh, pel, K0ld, K0ld / KC, w0h, w0l, bias, xh, xl);
    gemm_kernel<<<grid, 256, SMEM_TOTAL>>>(xh, xl, Hdim, Hdim / KC,
                                           whh + (size_t)0 * Hdim * Hdim, whl + (size_t)0 * Hdim * Hdim,
                                           bias + 1 * Hdim, yh, yl);
    gemm_kernel<<<grid, 256, SMEM_TOTAL>>>(yh, yl, Hdim, Hdim / KC,
                                           whh + (size_t)1 * Hdim * Hdim, whl + (size_t)1 * Hdim * Hdim,
                                           bias + 2 * Hdim, xh, xl);
    gemm_kernel<<<grid, 256, SMEM_TOTAL>>>(xh, xl, Hdim, Hdim / KC,
                                           whh + (size_t)2 * Hdim * Hdim, whl + (size_t)2 * Hdim * Hdim,
                                           bias + 3 * Hdim, yh, yl);
    gemm_kernel<<<grid, 256, SMEM_TOTAL>>>(yh, yl, Hdim, Hdim / KC,
                                           whh + (size_t)3 * Hdim * Hdim, whl + (size_t)3 * Hdim * Hdim,
                                           bias + 4 * Hdim, xh, xl);
    out_kernel<<<Bsz / 8, 256>>>(xh, xl, Wout, bout, out);
    tail_kernel<<<1, 256>>>(out, out_size);
}